// round 4
// baseline (speedup 1.0000x reference)
#include <cuda_runtime.h>
#include <cuda_fp16.h>

#define NN    50000
#define IND   512
#define HH    256
#define CC    8
#define EHH   64
#define E2C   400000
#define EDIR  800000
#define TT    10

// ---------------- scratch (device globals; no allocation allowed) ----------------
__device__ float  g_h[NN * HH];            // encoder hidden           51.2 MB
__device__ float  g_logphi[NN * CC];
__device__ float  g_phi[NN * CC];
__device__ int    g_deg[NN];
__device__ float  g_logdeg[NN];
__device__ float  g_wraw[E2C];
__device__ __half g_Kh[E2C * 64];          // per-pair kernel (fp16)   51.2 MB
__device__ float  g_norm[E2C];
__device__ float  g_m[EDIR * CC];          // messages                 25.6 MB
__device__ __half g_lfh[EDIR * CC];        // log factors (fp16)       12.8 MB
__device__ float  g_sumin2[2 * NN * CC];   // ping-pong node sums
__device__ float  g_R[64];
__device__ float  g_alpha;

// ---------------- small utility kernels ----------------
__global__ void zero_deg_kernel() {
    int i = blockIdx.x * 256 + threadIdx.x;
    if (i < NN) g_deg[i] = 0;
}

__global__ void zero_sumin_kernel(int which) {
    int i = blockIdx.x * 256 + threadIdx.x;
    if (i < NN * CC) g_sumin2[which * (NN * CC) + i] = 0.f;
}

__global__ void degcount_kernel(const int* __restrict__ ei) {
    int i = blockIdx.x * 256 + threadIdx.x;
    if (i < EDIR) atomicAdd(&g_deg[ei[i]], 1);
}

__global__ void degpost_kernel() {
    int i = blockIdx.x * 256 + threadIdx.x;
    if (i < NN) g_logdeg[i] = logf((float)g_deg[i] + 1.0f);
}

__global__ void prepR_kernel(const float* __restrict__ Rraw,
                             const float* __restrict__ rsl,
                             const float* __restrict__ ml) {
    int t = threadIdx.x;
    if (t < 64) {
        int c = t >> 3, d = t & 7;
        float rs = 0.5f * (Rraw[t] + Rraw[d * 8 + c]);
        float sc = log1pf(expf(rsl[0])) + 1e-6f;
        g_R[t] = sc * tanhf(rs);
    }
    if (t == 0) g_alpha = 1.5f / (1.f + expf(-ml[0]));
}

// ---------------- encoder GEMM: h = relu(X[50000,512] @ W[512,256] + b) ----------------
// Tile: 64 rows x 256 cols (ALL cols) per block -> X read exactly once.
// Static smem: 8KB + 32KB = 40KB.
__global__ __launch_bounds__(256) void enc_gemm_kernel(
    const float* __restrict__ X, const float* __restrict__ W,
    const float* __restrict__ bias)
{
    __shared__ float sA[32][64];    // [k][row]
    __shared__ float sB[32][256];   // [k][col]
    const int t    = threadIdx.x;
    const int row0 = blockIdx.x * 64;

    const int r0 = (t >> 5) * 8;        // 0..56
    const int cA = (t & 31) * 4;        // 0..124 ; second group at cA+128

    const int fa_m = t >> 2;            // 0..63
    const int fa_k = (t & 3) * 8;       // 0,8,16,24
    const int fb_k = t >> 3;            // 0..31
    const int fb_c = (t & 7) * 32;      // 0..224

    float acc[8][2][4];
#pragma unroll
    for (int i = 0; i < 8; i++)
#pragma unroll
        for (int g = 0; g < 2; g++)
#pragma unroll
            for (int j = 0; j < 4; j++) acc[i][g][j] = 0.f;

    const int  grow   = row0 + fa_m;
    const bool avalid = grow < NN;

    for (int k0 = 0; k0 < IND; k0 += 32) {
        float4 a0 = make_float4(0.f, 0.f, 0.f, 0.f), a1 = a0;
        if (avalid) {
            const float* xp = X + (size_t)grow * IND + k0 + fa_k;
            a0 = *(const float4*)xp;
            a1 = *(const float4*)(xp + 4);
        }
        sA[fa_k + 0][fa_m] = a0.x; sA[fa_k + 1][fa_m] = a0.y;
        sA[fa_k + 2][fa_m] = a0.z; sA[fa_k + 3][fa_m] = a0.w;
        sA[fa_k + 4][fa_m] = a1.x; sA[fa_k + 5][fa_m] = a1.y;
        sA[fa_k + 6][fa_m] = a1.z; sA[fa_k + 7][fa_m] = a1.w;

        const float* wp = W + (size_t)(k0 + fb_k) * HH + fb_c;
#pragma unroll
        for (int q = 0; q < 8; q++)
            *(float4*)&sB[fb_k][fb_c + q * 4] = *(const float4*)(wp + q * 4);
        __syncthreads();

#pragma unroll
        for (int kk = 0; kk < 32; kk++) {
            float4 aL = *(float4*)&sA[kk][r0];
            float4 aH = *(float4*)&sA[kk][r0 + 4];
            float4 b0 = *(float4*)&sB[kk][cA];
            float4 b1 = *(float4*)&sB[kk][cA + 128];
            float av[8] = {aL.x, aL.y, aL.z, aL.w, aH.x, aH.y, aH.z, aH.w};
#pragma unroll
            for (int i = 0; i < 8; i++) {
                acc[i][0][0] += av[i] * b0.x; acc[i][0][1] += av[i] * b0.y;
                acc[i][0][2] += av[i] * b0.z; acc[i][0][3] += av[i] * b0.w;
                acc[i][1][0] += av[i] * b1.x; acc[i][1][1] += av[i] * b1.y;
                acc[i][1][2] += av[i] * b1.z; acc[i][1][3] += av[i] * b1.w;
            }
        }
        __syncthreads();
    }

    float4 bsA = *(const float4*)&bias[cA];
    float4 bsB = *(const float4*)&bias[cA + 128];
#pragma unroll
    for (int i = 0; i < 8; i++) {
        int gr = row0 + r0 + i;
        if (gr < NN) {
            float4 o;
            o.x = fmaxf(acc[i][0][0] + bsA.x, 0.f);
            o.y = fmaxf(acc[i][0][1] + bsA.y, 0.f);
            o.z = fmaxf(acc[i][0][2] + bsA.z, 0.f);
            o.w = fmaxf(acc[i][0][3] + bsA.w, 0.f);
            *(float4*)&g_h[(size_t)gr * HH + cA] = o;
            o.x = fmaxf(acc[i][1][0] + bsB.x, 0.f);
            o.y = fmaxf(acc[i][1][1] + bsB.y, 0.f);
            o.z = fmaxf(acc[i][1][2] + bsB.z, 0.f);
            o.w = fmaxf(acc[i][1][3] + bsB.w, 0.f);
            *(float4*)&g_h[(size_t)gr * HH + cA + 128] = o;
        }
    }
}

// ---------------- log_phi + phi per node (warp per node) ----------------
__global__ __launch_bounds__(256) void logphi_kernel(
    const float* __restrict__ W2, const float* __restrict__ b2)
{
    __shared__ float sWT[CC * HH];   // transposed: [c][k]
    const int t = threadIdx.x;
    for (int i = t; i < HH * CC; i += 256) {
        int k = i >> 3, c = i & 7;
        sWT[c * HH + k] = W2[i];
    }
    __syncthreads();
    const int warp = t >> 5, lane = t & 31;
    const int node = blockIdx.x * 8 + warp;
    if (node >= NN) return;

    float acc[CC];
#pragma unroll
    for (int c = 0; c < CC; c++) acc[c] = 0.f;
    const float* hp = &g_h[(size_t)node * HH];
    for (int k = lane; k < HH; k += 32) {
        float hv = hp[k];
#pragma unroll
        for (int c = 0; c < CC; c++) acc[c] += hv * sWT[c * HH + k];
    }
#pragma unroll
    for (int c = 0; c < CC; c++) {
#pragma unroll
        for (int off = 16; off > 0; off >>= 1)
            acc[c] += __shfl_xor_sync(0xffffffffu, acc[c], off);
    }
    if (lane == 0) {
        float l[CC], mx = -1e30f;
#pragma unroll
        for (int c = 0; c < CC; c++) { l[c] = acc[c] + b2[c]; mx = fmaxf(mx, l[c]); }
        float s = 0.f;
#pragma unroll
        for (int c = 0; c < CC; c++) s += __expf(l[c] - mx);
        float lse = mx + __logf(s);
#pragma unroll
        for (int c = 0; c < CC; c++) {
            float lp = l[c] - lse;
            g_logphi[node * CC + c] = lp;
            g_phi[node * CC + c]    = __expf(lp);
        }
    }
}

// ---------------- edge MLP per undirected pair ----------------
// Tile: 128 pairs x 64 chans, 256 threads, 8x4 micro-tile, k-tile = 16.
// Each 16-k segment of h is gathered ONCE and feeds BOTH feature halves.
// Static smem: 24KB + 1.5KB.
__global__ __launch_bounds__(256) void edgemlp_kernel(
    const int* __restrict__ ei, const float* __restrict__ W1,
    const float* __restrict__ b1, const float* __restrict__ w2,
    const float* __restrict__ b2)
{
    __shared__ float sA0[16][128];
    __shared__ float sA1[16][128];
    __shared__ float sB0[16][64];
    __shared__ float sB1[16][64];
    __shared__ int   sS[128];
    __shared__ int   sD[128];
    __shared__ float sRed[128];

    const int t  = threadIdx.x;
    const int pb = blockIdx.x * 128;
    if (t < 128) {
        sS[t] = ei[pb + t];
        sD[t] = ei[EDIR + pb + t];
        sRed[t] = 0.f;
    }
    __syncthreads();

    const int r0 = (t >> 4) * 8;      // 0..120 (pair rows)
    const int c0 = (t & 15) * 4;      // 0..60  (channel cols)

    const int fe  = t >> 1;           // 0..127 (pair to gather)
    const int fk  = (t & 1) * 8;      // 0 or 8
    const int fbk = t >> 4;           // 0..15
    const int fbc = (t & 15) * 4;     // 0..60

    float acc[8][4];
#pragma unroll
    for (int i = 0; i < 8; i++)
#pragma unroll
        for (int j = 0; j < 4; j++) acc[i][j] = 0.f;

    const float* hsp = &g_h[(size_t)sS[fe] * HH];
    const float* hdp = &g_h[(size_t)sD[fe] * HH];

    for (int seg = 0; seg < 16; seg++) {
        const int k0 = seg * 16;

        float4 s0 = *(const float4*)(hsp + k0 + fk);
        float4 s1 = *(const float4*)(hsp + k0 + fk + 4);
        float4 d0 = *(const float4*)(hdp + k0 + fk);
        float4 d1 = *(const float4*)(hdp + k0 + fk + 4);
        float sv[8] = {s0.x, s0.y, s0.z, s0.w, s1.x, s1.y, s1.z, s1.w};
        float dv[8] = {d0.x, d0.y, d0.z, d0.w, d1.x, d1.y, d1.z, d1.w};
#pragma unroll
        for (int i = 0; i < 8; i++) {
            sA0[fk + i][fe] = sv[i] * dv[i];
            sA1[fk + i][fe] = fabsf(sv[i] - dv[i]);
        }

        const float* wp0 = W1 + (size_t)(k0 + fbk) * EHH + fbc;
        const float* wp1 = W1 + (size_t)(256 + k0 + fbk) * EHH + fbc;
        *(float4*)&sB0[fbk][fbc] = *(const float4*)wp0;
        *(float4*)&sB1[fbk][fbc] = *(const float4*)wp1;
        __syncthreads();

#pragma unroll
        for (int kk = 0; kk < 16; kk++) {
            {
                float4 aL = *(float4*)&sA0[kk][r0];
                float4 aH = *(float4*)&sA0[kk][r0 + 4];
                float4 b  = *(float4*)&sB0[kk][c0];
                float av[8] = {aL.x, aL.y, aL.z, aL.w, aH.x, aH.y, aH.z, aH.w};
#pragma unroll
                for (int i = 0; i < 8; i++) {
                    acc[i][0] += av[i] * b.x; acc[i][1] += av[i] * b.y;
                    acc[i][2] += av[i] * b.z; acc[i][3] += av[i] * b.w;
                }
            }
            {
                float4 aL = *(float4*)&sA1[kk][r0];
                float4 aH = *(float4*)&sA1[kk][r0 + 4];
                float4 b  = *(float4*)&sB1[kk][c0];
                float av[8] = {aL.x, aL.y, aL.z, aL.w, aH.x, aH.y, aH.z, aH.w};
#pragma unroll
                for (int i = 0; i < 8; i++) {
                    acc[i][0] += av[i] * b.x; acc[i][1] += av[i] * b.y;
                    acc[i][2] += av[i] * b.z; acc[i][3] += av[i] * b.w;
                }
            }
        }
        __syncthreads();
    }

    // struct features (rows 512, 513 of W1)
    float w1s0[4], w1s1[4];
#pragma unroll
    for (int j = 0; j < 4; j++) {
        w1s0[j] = W1[512 * EHH + c0 + j];
        w1s1[j] = W1[513 * EHH + c0 + j];
    }
#pragma unroll
    for (int i = 0; i < 8; i++) {
        int e = r0 + i;
        float la = g_logdeg[sS[e]], lb = g_logdeg[sD[e]];
        float t0 = la + lb, t1 = fabsf(la - lb);
#pragma unroll
        for (int j = 0; j < 4; j++) acc[i][j] += t0 * w1s0[j] + t1 * w1s1[j];
    }

    // epilogue: relu + dot with w2, reduce across 16 chan-groups
    float bb[4], ww[4];
#pragma unroll
    for (int j = 0; j < 4; j++) { bb[j] = b1[c0 + j]; ww[j] = w2[c0 + j]; }
#pragma unroll
    for (int i = 0; i < 8; i++) {
        float part = 0.f;
#pragma unroll
        for (int j = 0; j < 4; j++) part += fmaxf(acc[i][j] + bb[j], 0.f) * ww[j];
        atomicAdd(&sRed[r0 + i], part);
    }
    __syncthreads();
    if (t < 128) g_wraw[pb + t] = sRed[t] + b2[0];
}

// ---------------- per-pair preparation: w, K (fp16), edge_norm, m init ----------------
__global__ __launch_bounds__(256) void edgeprep_kernel(const int* __restrict__ ei)
{
    __shared__ float sR[64];
    if (threadIdx.x < 64) sR[threadIdx.x] = g_R[threadIdx.x];
    __syncthreads();
    int p = blockIdx.x * 256 + threadIdx.x;
    if (p >= E2C) return;
    int s = ei[p], d = ei[EDIR + p];
    float w = 0.8f / (1.f + __expf(-g_wraw[p]));
    __half2* kp = (__half2*)&g_Kh[(size_t)p * 64];
#pragma unroll
    for (int i = 0; i < 32; i++) {
        float2 v;
        v.x = __expf(w * sR[2 * i + 0]);
        v.y = __expf(w * sR[2 * i + 1]);
        kp[i] = __float22half2_rn(v);
    }
    float dcs = fmaxf((float)g_deg[s], 1.f);
    float dcd = fmaxf((float)g_deg[d], 1.f);
    g_norm[p] = rsqrtf(dcs * dcd);

    const float4* ps = (const float4*)&g_phi[s * CC];
    float4* mp = (float4*)&g_m[(size_t)p * CC];
    mp[0] = ps[0]; mp[1] = ps[1];
    const float4* pd = (const float4*)&g_phi[d * CC];
    float4* mq = (float4*)&g_m[(size_t)(E2C + p) * CC];
    mq[0] = pd[0]; mq[1] = pd[1];
}

// vector reduction into global memory (sm_90+)
__device__ __forceinline__ void red_add_v4(float* ptr, float a, float b, float c, float d)
{
    unsigned long long g = (unsigned long long)__cvta_generic_to_global(ptr);
    asm volatile("red.global.add.v4.f32 [%0], {%1, %2, %3, %4};"
                 :: "l"(g), "f"(a), "f"(b), "f"(c), "f"(d) : "memory");
}

// f = m @ K (fp16 K, fp32 accum) for both directions of pair p
__device__ __forceinline__ void pair_factor(int p, const float* m0, const float* m1,
                                            float* f0, float* f1)
{
#pragma unroll
    for (int j = 0; j < 8; j++) { f0[j] = 0.f; f1[j] = 0.f; }
    const __half2* Kp = (const __half2*)&g_Kh[(size_t)p * 64];
#pragma unroll
    for (int c = 0; c < 8; c++) {
#pragma unroll
        for (int q = 0; q < 4; q++) {
            float2 kv = __half22float2(Kp[c * 4 + q]);
            f0[2 * q + 0] += m0[c] * kv.x; f0[2 * q + 1] += m0[c] * kv.y;
            f1[2 * q + 0] += m1[c] * kv.x; f1[2 * q + 1] += m1[c] * kv.y;
        }
    }
}

__device__ __forceinline__ void store_lf_red(int p, int s, int d, float nrm,
                                             const float* f0, const float* f1,
                                             float* Snew)
{
    float lf0[8], lf1[8];
#pragma unroll
    for (int j = 0; j < 8; j++) {
        lf0[j] = __logf(fmaxf(f0[j], 1e-12f)) * nrm;
        lf1[j] = __logf(fmaxf(f1[j], 1e-12f)) * nrm;
    }
    __half2* o0 = (__half2*)&g_lfh[(size_t)p * 8];
    __half2* o1 = (__half2*)&g_lfh[(size_t)(E2C + p) * 8];
#pragma unroll
    for (int q = 0; q < 4; q++) {
        o0[q] = __float22half2_rn(make_float2(lf0[2 * q], lf0[2 * q + 1]));
        o1[q] = __float22half2_rn(make_float2(lf1[2 * q], lf1[2 * q + 1]));
    }
    red_add_v4(&Snew[d * 8 + 0], lf0[0], lf0[1], lf0[2], lf0[3]);  // edge p: s->d
    red_add_v4(&Snew[d * 8 + 4], lf0[4], lf0[5], lf0[6], lf0[7]);
    red_add_v4(&Snew[s * 8 + 0], lf1[0], lf1[1], lf1[2], lf1[3]);  // edge p+E2: d->s
    red_add_v4(&Snew[s * 8 + 4], lf1[4], lf1[5], lf1[6], lf1[7]);
}

// ---------------- BP init: f from m_0, lf_0, sum_in_0 -> buf[0] ----------------
__global__ __launch_bounds__(256) void bpA0_kernel(const int* __restrict__ ei)
{
    int p = blockIdx.x * 256 + threadIdx.x;
    if (p >= E2C) return;
    float m0[8], m1[8];
    {
        const float4* a = (const float4*)&g_m[(size_t)p * 8];
        float4 x0 = a[0], x1 = a[1];
        m0[0] = x0.x; m0[1] = x0.y; m0[2] = x0.z; m0[3] = x0.w;
        m0[4] = x1.x; m0[5] = x1.y; m0[6] = x1.z; m0[7] = x1.w;
        const float4* b = (const float4*)&g_m[(size_t)(E2C + p) * 8];
        float4 y0 = b[0], y1 = b[1];
        m1[0] = y0.x; m1[1] = y0.y; m1[2] = y0.z; m1[3] = y0.w;
        m1[4] = y1.x; m1[5] = y1.y; m1[6] = y1.z; m1[7] = y1.w;
    }
    float f0[8], f1[8];
    pair_factor(p, m0, m1, f0, f1);
    int s = ei[p], d = ei[EDIR + p];
    store_lf_red(p, s, d, g_norm[p], f0, f1, g_sumin2);
}

// ---------------- fused BP step: bpB(t) + bpA(t) ----------------
// Reads sum_in from buf[rd] (complete), lf_{t-1}, m_{t-1}; produces m_t,
// lf_t, and accumulates sum_in_t into buf[wr] (pre-zeroed).
__device__ __forceinline__ void update_row(float* m, const float* lp, const float* S,
                                           const float* lf, float alpha)
{
    float lo[8], mx = -1e30f;
#pragma unroll
    for (int c = 0; c < 8; c++) {
        lo[c] = lp[c] + alpha * (S[c] - lf[c]);
        mx = fmaxf(mx, lo[c]);
    }
    float ex[8], sum = 0.f;
#pragma unroll
    for (int c = 0; c < 8; c++) { ex[c] = __expf(lo[c] - mx); sum += ex[c]; }
    float inv = __fdividef(1.f, sum);
    float s2 = 0.f;
#pragma unroll
    for (int c = 0; c < 8; c++) {
        m[c] = 0.8f * m[c] + 0.2f * ex[c] * inv;
        m[c] = fmaxf(m[c], 1e-12f);
        s2 += m[c];
    }
    float i2 = __fdividef(1.f, s2);
#pragma unroll
    for (int c = 0; c < 8; c++) m[c] *= i2;
}

__global__ __launch_bounds__(256) void bpF_kernel(const int* __restrict__ ei,
                                                  int rd, int wr)
{
    int p = blockIdx.x * 256 + threadIdx.x;
    if (p >= E2C) return;
    int s = ei[p], d = ei[EDIR + p];
    const float* Sold = g_sumin2 + (size_t)rd * (NN * CC);
    float*       Snew = g_sumin2 + (size_t)wr * (NN * CC);
    float alpha = g_alpha;

    // old log-factors (fp16)
    float lf0[8], lf1[8];
    {
        const __half2* a = (const __half2*)&g_lfh[(size_t)p * 8];
        const __half2* b = (const __half2*)&g_lfh[(size_t)(E2C + p) * 8];
#pragma unroll
        for (int q = 0; q < 4; q++) {
            float2 u = __half22float2(a[q]);
            float2 v = __half22float2(b[q]);
            lf0[2 * q] = u.x; lf0[2 * q + 1] = u.y;
            lf1[2 * q] = v.x; lf1[2 * q + 1] = v.y;
        }
    }
    float Ss[8], Sd[8], lps[8], lpd[8];
    {
        const float4* c4 = (const float4*)&Sold[s * 8];
        float4 z0 = c4[0], z1 = c4[1];
        Ss[0] = z0.x; Ss[1] = z0.y; Ss[2] = z0.z; Ss[3] = z0.w;
        Ss[4] = z1.x; Ss[5] = z1.y; Ss[6] = z1.z; Ss[7] = z1.w;
        const float4* d4 = (const float4*)&Sold[d * 8];
        float4 w0 = d4[0], w1 = d4[1];
        Sd[0] = w0.x; Sd[1] = w0.y; Sd[2] = w0.z; Sd[3] = w0.w;
        Sd[4] = w1.x; Sd[5] = w1.y; Sd[6] = w1.z; Sd[7] = w1.w;
        const float4* e4 = (const float4*)&g_logphi[s * 8];
        float4 u0 = e4[0], u1 = e4[1];
        lps[0] = u0.x; lps[1] = u0.y; lps[2] = u0.z; lps[3] = u0.w;
        lps[4] = u1.x; lps[5] = u1.y; lps[6] = u1.z; lps[7] = u1.w;
        const float4* f4 = (const float4*)&g_logphi[d * 8];
        float4 v0 = f4[0], v1 = f4[1];
        lpd[0] = v0.x; lpd[1] = v0.y; lpd[2] = v0.z; lpd[3] = v0.w;
        lpd[4] = v1.x; lpd[5] = v1.y; lpd[6] = v1.z; lpd[7] = v1.w;
    }

    // load messages, update in registers
    float m0[8], m1[8];
    {
        float4* a = (float4*)&g_m[(size_t)p * 8];
        float4 x0 = a[0], x1 = a[1];
        m0[0] = x0.x; m0[1] = x0.y; m0[2] = x0.z; m0[3] = x0.w;
        m0[4] = x1.x; m0[5] = x1.y; m0[6] = x1.z; m0[7] = x1.w;
        float4* b = (float4*)&g_m[(size_t)(E2C + p) * 8];
        float4 y0 = b[0], y1 = b[1];
        m1[0] = y0.x; m1[1] = y0.y; m1[2] = y0.z; m1[3] = y0.w;
        m1[4] = y1.x; m1[5] = y1.y; m1[6] = y1.z; m1[7] = y1.w;
    }
    update_row(m0, lps, Ss, lf1, alpha);   // edge p:    src=s, rev lf = lf1
    update_row(m1, lpd, Sd, lf0, alpha);   // edge p+E2: src=d, rev lf = lf0
    {
        float4* a = (float4*)&g_m[(size_t)p * 8];
        a[0] = make_float4(m0[0], m0[1], m0[2], m0[3]);
        a[1] = make_float4(m0[4], m0[5], m0[6], m0[7]);
        float4* b = (float4*)&g_m[(size_t)(E2C + p) * 8];
        b[0] = make_float4(m1[0], m1[1], m1[2], m1[3]);
        b[1] = make_float4(m1[4], m1[5], m1[6], m1[7]);
    }

    // immediately compute this iteration's factors + scatter
    float f0[8], f1[8];
    pair_factor(p, m0, m1, f0, f1);
    store_lf_red(p, s, d, g_norm[p], f0, f1, Snew);
}

// ---------------- final beliefs (reads buf[0]) ----------------
__global__ void beliefs_kernel(float* __restrict__ out)
{
    int n = blockIdx.x * 256 + threadIdx.x;
    if (n >= NN) return;
    float alpha = g_alpha;
    const float* lp = &g_logphi[n * 8];
    const float* S  = &g_sumin2[n * 8];
    float l[8], mx = -1e30f;
#pragma unroll
    for (int c = 0; c < 8; c++) { l[c] = lp[c] + alpha * S[c]; mx = fmaxf(mx, l[c]); }
    float ex[8], sum = 0.f;
#pragma unroll
    for (int c = 0; c < 8; c++) { ex[c] = __expf(l[c] - mx); sum += ex[c]; }
    float inv = __fdividef(1.f, sum);
    float4* o = (float4*)&out[n * 8];
    o[0] = make_float4(ex[0] * inv, ex[1] * inv, ex[2] * inv, ex[3] * inv);
    o[1] = make_float4(ex[4] * inv, ex[5] * inv, ex[6] * inv, ex[7] * inv);
}

// ---------------- driver ----------------
extern "C" void kernel_launch(void* const* d_in, const int* in_sizes, int n_in,
                              void* d_out, int out_size)
{
    (void)in_sizes; (void)n_in; (void)out_size;
    const float* x       = (const float*)d_in[0];
    const int*   ei      = (const int*)d_in[1];
    // d_in[2] = rev: structurally known (i <-> i+E2), unused
    const float* enc_w1  = (const float*)d_in[3];
    const float* enc_b1  = (const float*)d_in[4];
    const float* enc_w2  = (const float*)d_in[5];
    const float* enc_b2  = (const float*)d_in[6];
    const float* edge_w1 = (const float*)d_in[7];
    const float* edge_b1 = (const float*)d_in[8];
    const float* edge_w2 = (const float*)d_in[9];
    const float* edge_b2 = (const float*)d_in[10];
    const float* R_raw   = (const float*)d_in[11];
    const float* rsl     = (const float*)d_in[12];
    const float* ml      = (const float*)d_in[13];
    float* out = (float*)d_out;

    const int ZS = (NN * CC + 255) / 256;
    const int PB = (E2C + 255) / 256;

    zero_deg_kernel<<<(NN + 255) / 256, 256>>>();
    enc_gemm_kernel<<<(NN + 63) / 64, 256>>>(x, enc_w1, enc_b1);
    logphi_kernel<<<(NN + 7) / 8, 256>>>(enc_w2, enc_b2);
    degcount_kernel<<<EDIR / 256, 256>>>(ei);
    degpost_kernel<<<(NN + 255) / 256, 256>>>();
    prepR_kernel<<<1, 64>>>(R_raw, rsl, ml);
    edgemlp_kernel<<<E2C / 128, 256>>>(ei, edge_w1, edge_b1, edge_w2, edge_b2);
    edgeprep_kernel<<<PB, 256>>>(ei);

    // t = 0: factors + sum_in from initial messages -> buf 0
    zero_sumin_kernel<<<ZS, 256>>>(0);
    bpA0_kernel<<<PB, 256>>>(ei);

    // t = 1..10: fused update + re-factor, ping-ponging sum_in buffers.
    // After t = 10 the freshest sum_in (from m_10) is in buf 0.
    for (int t = 1; t <= TT; t++) {
        int rd = (t - 1) & 1, wr = t & 1;
        zero_sumin_kernel<<<ZS, 256>>>(wr);
        bpF_kernel<<<PB, 256>>>(ei, rd, wr);
    }
    beliefs_kernel<<<(NN + 255) / 256, 256>>>(out);
}

// round 12
// speedup vs baseline: 1.0301x; 1.0301x over previous
#include <cuda_runtime.h>
#include <cuda_fp16.h>

#define NN    50000
#define IND   512
#define HH    256
#define CC    8
#define EHH   64
#define E2C   400000
#define EDIR  800000
#define TT    10

// ---------------- scratch (device globals; no allocation allowed) ----------------
__device__ float  g_h[NN * HH];            // encoder hidden           51.2 MB
__device__ float  g_logphi[NN * CC];
__device__ float  g_phi[NN * CC];
__device__ int    g_deg[NN];
__device__ float  g_logdeg[NN];
__device__ float  g_wraw[E2C];
__device__ __half g_Kh[E2C * 64];          // per-pair kernel (fp16)   51.2 MB
__device__ float  g_norm[E2C];
__device__ float  g_m[EDIR * CC];          // messages                 25.6 MB
__device__ __half g_lfh[EDIR * CC];        // log factors (fp16)       12.8 MB
__device__ float  g_sumin2[2 * NN * CC];   // ping-pong node sums
__device__ float  g_R[64];
__device__ float  g_alpha;

// ---------------- small utility kernels ----------------
__global__ void degcount_kernel(const int* __restrict__ ei) {
    int i = blockIdx.x * 256 + threadIdx.x;
    if (i < EDIR) atomicAdd(&g_deg[ei[i]], 1);
}

__global__ void degpost_kernel() {
    int i = blockIdx.x * 256 + threadIdx.x;
    if (i < NN) g_logdeg[i] = logf((float)g_deg[i] + 1.0f);
}

__global__ void prepR_kernel(const float* __restrict__ Rraw,
                             const float* __restrict__ rsl,
                             const float* __restrict__ ml) {
    int t = threadIdx.x;
    if (t < 64) {
        int c = t >> 3, d = t & 7;
        float rs = 0.5f * (Rraw[t] + Rraw[d * 8 + c]);
        float sc = log1pf(expf(rsl[0])) + 1e-6f;
        g_R[t] = sc * tanhf(rs);
    }
    if (t == 0) g_alpha = 1.5f / (1.f + expf(-ml[0]));
}

// ---------------- encoder GEMM: h = relu(X[50000,512] @ W[512,256] + b) ----------------
__global__ __launch_bounds__(256) void enc_gemm_kernel(
    const float* __restrict__ X, const float* __restrict__ W,
    const float* __restrict__ bias)
{
    __shared__ float sA[32][64];    // [k][row]
    __shared__ float sB[32][256];   // [k][col]
    const int t    = threadIdx.x;
    const int row0 = blockIdx.x * 64;

    const int r0 = (t >> 5) * 8;        // 0..56
    const int cA = (t & 31) * 4;        // 0..124 ; second group at cA+128

    const int fa_m = t >> 2;            // 0..63
    const int fa_k = (t & 3) * 8;       // 0,8,16,24
    const int fb_k = t >> 3;            // 0..31
    const int fb_c = (t & 7) * 32;      // 0..224

    float acc[8][2][4];
#pragma unroll
    for (int i = 0; i < 8; i++)
#pragma unroll
        for (int g = 0; g < 2; g++)
#pragma unroll
            for (int j = 0; j < 4; j++) acc[i][g][j] = 0.f;

    const int  grow   = row0 + fa_m;
    const bool avalid = grow < NN;

    for (int k0 = 0; k0 < IND; k0 += 32) {
        float4 a0 = make_float4(0.f, 0.f, 0.f, 0.f), a1 = a0;
        if (avalid) {
            const float* xp = X + (size_t)grow * IND + k0 + fa_k;
            a0 = *(const float4*)xp;
            a1 = *(const float4*)(xp + 4);
        }
        sA[fa_k + 0][fa_m] = a0.x; sA[fa_k + 1][fa_m] = a0.y;
        sA[fa_k + 2][fa_m] = a0.z; sA[fa_k + 3][fa_m] = a0.w;
        sA[fa_k + 4][fa_m] = a1.x; sA[fa_k + 5][fa_m] = a1.y;
        sA[fa_k + 6][fa_m] = a1.z; sA[fa_k + 7][fa_m] = a1.w;

        const float* wp = W + (size_t)(k0 + fb_k) * HH + fb_c;
#pragma unroll
        for (int q = 0; q < 8; q++)
            *(float4*)&sB[fb_k][fb_c + q * 4] = *(const float4*)(wp + q * 4);
        __syncthreads();

#pragma unroll
        for (int kk = 0; kk < 32; kk++) {
            float4 aL = *(float4*)&sA[kk][r0];
            float4 aH = *(float4*)&sA[kk][r0 + 4];
            float4 b0 = *(float4*)&sB[kk][cA];
            float4 b1 = *(float4*)&sB[kk][cA + 128];
            float av[8] = {aL.x, aL.y, aL.z, aL.w, aH.x, aH.y, aH.z, aH.w};
#pragma unroll
            for (int i = 0; i < 8; i++) {
                acc[i][0][0] += av[i] * b0.x; acc[i][0][1] += av[i] * b0.y;
                acc[i][0][2] += av[i] * b0.z; acc[i][0][3] += av[i] * b0.w;
                acc[i][1][0] += av[i] * b1.x; acc[i][1][1] += av[i] * b1.y;
                acc[i][1][2] += av[i] * b1.z; acc[i][1][3] += av[i] * b1.w;
            }
        }
        __syncthreads();
    }

    float4 bsA = *(const float4*)&bias[cA];
    float4 bsB = *(const float4*)&bias[cA + 128];
#pragma unroll
    for (int i = 0; i < 8; i++) {
        int gr = row0 + r0 + i;
        if (gr < NN) {
            float4 o;
            o.x = fmaxf(acc[i][0][0] + bsA.x, 0.f);
            o.y = fmaxf(acc[i][0][1] + bsA.y, 0.f);
            o.z = fmaxf(acc[i][0][2] + bsA.z, 0.f);
            o.w = fmaxf(acc[i][0][3] + bsA.w, 0.f);
            *(float4*)&g_h[(size_t)gr * HH + cA] = o;
            o.x = fmaxf(acc[i][1][0] + bsB.x, 0.f);
            o.y = fmaxf(acc[i][1][1] + bsB.y, 0.f);
            o.z = fmaxf(acc[i][1][2] + bsB.z, 0.f);
            o.w = fmaxf(acc[i][1][3] + bsB.w, 0.f);
            *(float4*)&g_h[(size_t)gr * HH + cA + 128] = o;
        }
    }
}

// ---------------- log_phi + phi per node (warp per node) ----------------
__global__ __launch_bounds__(256) void logphi_kernel(
    const float* __restrict__ W2, const float* __restrict__ b2)
{
    __shared__ float sWT[CC * HH];   // transposed: [c][k]
    const int t = threadIdx.x;
    for (int i = t; i < HH * CC; i += 256) {
        int k = i >> 3, c = i & 7;
        sWT[c * HH + k] = W2[i];
    }
    __syncthreads();
    const int warp = t >> 5, lane = t & 31;
    const int node = blockIdx.x * 8 + warp;
    if (node >= NN) return;

    float acc[CC];
#pragma unroll
    for (int c = 0; c < CC; c++) acc[c] = 0.f;
    const float* hp = &g_h[(size_t)node * HH];
    for (int k = lane; k < HH; k += 32) {
        float hv = hp[k];
#pragma unroll
        for (int c = 0; c < CC; c++) acc[c] += hv * sWT[c * HH + k];
    }
#pragma unroll
    for (int c = 0; c < CC; c++) {
#pragma unroll
        for (int off = 16; off > 0; off >>= 1)
            acc[c] += __shfl_xor_sync(0xffffffffu, acc[c], off);
    }
    if (lane == 0) {
        float l[CC], mx = -1e30f;
#pragma unroll
        for (int c = 0; c < CC; c++) { l[c] = acc[c] + b2[c]; mx = fmaxf(mx, l[c]); }
        float s = 0.f;
#pragma unroll
        for (int c = 0; c < CC; c++) s += __expf(l[c] - mx);
        float lse = mx + __logf(s);
#pragma unroll
        for (int c = 0; c < CC; c++) {
            float lp = l[c] - lse;
            g_logphi[node * CC + c] = lp;
            g_phi[node * CC + c]    = __expf(lp);
        }
    }
}

// ---------------- edge MLP per undirected pair (fp16 HFMA2, k-pair packed) ----
// Tile: 256 pairs x 64 chans, 256 threads, 8x8 micro-tile (one half2 acc per
// output holding even/odd-k partials). Both feature halves (product, absdiff)
// are built from ONE gather of h and accumulate into the SAME acc.
__global__ __launch_bounds__(256) void edgemlp_kernel(
    const int* __restrict__ ei, const float* __restrict__ W1,
    const float* __restrict__ b1, const float* __restrict__ w2,
    const float* __restrict__ b2)
{
    __shared__ __half2 sA0[8][256];   // [k-pair][pair]
    __shared__ __half2 sA1[8][256];
    __shared__ __half2 sB0[8][64];    // [k-pair][chan]
    __shared__ __half2 sB1[8][64];
    __shared__ int   sS[256];
    __shared__ int   sD[256];
    __shared__ float sRed[256];

    const int t  = threadIdx.x;
    const int pb = blockIdx.x * 256;
    {
        int q  = pb + t;
        int qc = q < E2C ? q : (E2C - 1);
        sS[t] = ei[qc];
        sD[t] = ei[EDIR + qc];
        sRed[t] = 0.f;
    }
    __syncthreads();

    const int r0 = (t >> 3) * 8;      // pair-row group: 0..248
    const int c0 = (t & 7) * 8;       // channel group: 0..56 (8 chans)

    // B-fill mapping: 2 entries per thread per feature
    const int bi0 = t * 2, bi1 = t * 2 + 1;
    const int bkp0 = bi0 >> 6, bch0 = bi0 & 63;
    const int bkp1 = bi1 >> 6, bch1 = bi1 & 63;

    __half2 acc[8][8];
    const __half2 hz = __floats2half2_rn(0.f, 0.f);
#pragma unroll
    for (int i = 0; i < 8; i++)
#pragma unroll
        for (int j = 0; j < 8; j++) acc[i][j] = hz;

    const float* hsp = &g_h[(size_t)sS[t] * HH];
    const float* hdp = &g_h[(size_t)sD[t] * HH];

    for (int seg = 0; seg < 16; seg++) {
        const int k0 = seg * 16;

        // gather 16 k of hs/hd once (fp32 from L2), build both feature halves
        float sv[16], dv[16];
#pragma unroll
        for (int q = 0; q < 4; q++) {
            float4 sx = *(const float4*)(hsp + k0 + q * 4);
            float4 dx = *(const float4*)(hdp + k0 + q * 4);
            sv[q*4+0]=sx.x; sv[q*4+1]=sx.y; sv[q*4+2]=sx.z; sv[q*4+3]=sx.w;
            dv[q*4+0]=dx.x; dv[q*4+1]=dx.y; dv[q*4+2]=dx.z; dv[q*4+3]=dx.w;
        }
#pragma unroll
        for (int q = 0; q < 8; q++) {
            float px = sv[2*q]   * dv[2*q];
            float py = sv[2*q+1] * dv[2*q+1];
            sA0[q][t] = __floats2half2_rn(px, py);
            float ax = fabsf(sv[2*q]   - dv[2*q]);
            float ay = fabsf(sv[2*q+1] - dv[2*q+1]);
            sA1[q][t] = __floats2half2_rn(ax, ay);
        }

        // B tiles: pack (k, k+1) per channel; feature0 rows [k0..], feature1 rows [256+k0..]
        {
            int kr0 = k0 + 2 * bkp0;
            sB0[bkp0][bch0] = __floats2half2_rn(W1[(size_t)kr0 * EHH + bch0],
                                                W1[(size_t)(kr0 + 1) * EHH + bch0]);
            sB1[bkp0][bch0] = __floats2half2_rn(W1[(size_t)(256 + kr0) * EHH + bch0],
                                                W1[(size_t)(257 + kr0) * EHH + bch0]);
            int kr1 = k0 + 2 * bkp1;
            sB0[bkp1][bch1] = __floats2half2_rn(W1[(size_t)kr1 * EHH + bch1],
                                                W1[(size_t)(kr1 + 1) * EHH + bch1]);
            sB1[bkp1][bch1] = __floats2half2_rn(W1[(size_t)(256 + kr1) * EHH + bch1],
                                                W1[(size_t)(257 + kr1) * EHH + bch1]);
        }
        __syncthreads();

#pragma unroll
        for (int kk = 0; kk < 8; kk++) {
            __half2 a0[8], a1[8], b0[8], b1[8];
            *(uint4*)&a0[0] = *(const uint4*)&sA0[kk][r0];
            *(uint4*)&a0[4] = *(const uint4*)&sA0[kk][r0 + 4];
            *(uint4*)&a1[0] = *(const uint4*)&sA1[kk][r0];
            *(uint4*)&a1[4] = *(const uint4*)&sA1[kk][r0 + 4];
            *(uint4*)&b0[0] = *(const uint4*)&sB0[kk][c0];
            *(uint4*)&b0[4] = *(const uint4*)&sB0[kk][c0 + 4];
            *(uint4*)&b1[0] = *(const uint4*)&sB1[kk][c0];
            *(uint4*)&b1[4] = *(const uint4*)&sB1[kk][c0 + 4];
#pragma unroll
            for (int i = 0; i < 8; i++)
#pragma unroll
                for (int j = 0; j < 8; j++) {
                    acc[i][j] = __hfma2(a0[i], b0[j], acc[i][j]);
                    acc[i][j] = __hfma2(a1[i], b1[j], acc[i][j]);
                }
        }
        __syncthreads();
    }

    // epilogue: horizontal add, struct features, relu + w2 dot, row reduce
    float bb[8], ww[8], w1s0[8], w1s1[8];
#pragma unroll
    for (int j = 0; j < 8; j++) {
        bb[j]   = b1[c0 + j];
        ww[j]   = w2[c0 + j];
        w1s0[j] = W1[512 * EHH + c0 + j];
        w1s1[j] = W1[513 * EHH + c0 + j];
    }
#pragma unroll
    for (int i = 0; i < 8; i++) {
        int e = r0 + i;
        float la = g_logdeg[sS[e]], lb = g_logdeg[sD[e]];
        float t0 = la + lb, t1 = fabsf(la - lb);
        float part = 0.f;
#pragma unroll
        for (int j = 0; j < 8; j++) {
            float2 v = __half22float2(acc[i][j]);
            float o = v.x + v.y + t0 * w1s0[j] + t1 * w1s1[j];
            part += fmaxf(o + bb[j], 0.f) * ww[j];
        }
        atomicAdd(&sRed[e], part);
    }
    __syncthreads();
    if (pb + t < E2C) g_wraw[pb + t] = sRed[t] + b2[0];
}

// ---------------- per-pair preparation: w, K (fp16), edge_norm, m init ----------------
__global__ __launch_bounds__(256) void edgeprep_kernel(const int* __restrict__ ei)
{
    __shared__ float sR[64];
    if (threadIdx.x < 64) sR[threadIdx.x] = g_R[threadIdx.x];
    __syncthreads();
    int p = blockIdx.x * 256 + threadIdx.x;
    if (p >= E2C) return;
    int s = ei[p], d = ei[EDIR + p];
    float w = 0.8f / (1.f + __expf(-g_wraw[p]));
    __half2* kp = (__half2*)&g_Kh[(size_t)p * 64];
#pragma unroll
    for (int i = 0; i < 32; i++) {
        float2 v;
        v.x = __expf(w * sR[2 * i + 0]);
        v.y = __expf(w * sR[2 * i + 1]);
        kp[i] = __float22half2_rn(v);
    }
    float dcs = fmaxf((float)g_deg[s], 1.f);
    float dcd = fmaxf((float)g_deg[d], 1.f);
    g_norm[p] = rsqrtf(dcs * dcd);

    const float4* ps = (const float4*)&g_phi[s * CC];
    float4* mp = (float4*)&g_m[(size_t)p * CC];
    mp[0] = ps[0]; mp[1] = ps[1];
    const float4* pd = (const float4*)&g_phi[d * CC];
    float4* mq = (float4*)&g_m[(size_t)(E2C + p) * CC];
    mq[0] = pd[0]; mq[1] = pd[1];
}

// vector reduction into global memory (sm_90+)
__device__ __forceinline__ void red_add_v4(float* ptr, float a, float b, float c, float d)
{
    unsigned long long g = (unsigned long long)__cvta_generic_to_global(ptr);
    asm volatile("red.global.add.v4.f32 [%0], {%1, %2, %3, %4};"
                 :: "l"(g), "f"(a), "f"(b), "f"(c), "f"(d) : "memory");
}

// f = m @ K (fp16 K, fp32 accum) for both directions of pair p
__device__ __forceinline__ void pair_factor(int p, const float* m0, const float* m1,
                                            float* f0, float* f1)
{
#pragma unroll
    for (int j = 0; j < 8; j++) { f0[j] = 0.f; f1[j] = 0.f; }
    const __half2* Kp = (const __half2*)&g_Kh[(size_t)p * 64];
#pragma unroll
    for (int c = 0; c < 8; c++) {
#pragma unroll
        for (int q = 0; q < 4; q++) {
            float2 kv = __half22float2(Kp[c * 4 + q]);
            f0[2 * q + 0] += m0[c] * kv.x; f0[2 * q + 1] += m0[c] * kv.y;
            f1[2 * q + 0] += m1[c] * kv.x; f1[2 * q + 1] += m1[c] * kv.y;
        }
    }
}

__device__ __forceinline__ void store_lf_red(int p, int s, int d, float nrm,
                                             const float* f0, const float* f1,
                                             float* Snew)
{
    float lf0[8], lf1[8];
#pragma unroll
    for (int j = 0; j < 8; j++) {
        lf0[j] = __logf(fmaxf(f0[j], 1e-12f)) * nrm;
        lf1[j] = __logf(fmaxf(f1[j], 1e-12f)) * nrm;
    }
    __half2* o0 = (__half2*)&g_lfh[(size_t)p * 8];
    __half2* o1 = (__half2*)&g_lfh[(size_t)(E2C + p) * 8];
#pragma unroll
    for (int q = 0; q < 4; q++) {
        o0[q] = __float22half2_rn(make_float2(lf0[2 * q], lf0[2 * q + 1]));
        o1[q] = __float22half2_rn(make_float2(lf1[2 * q], lf1[2 * q + 1]));
    }
    red_add_v4(&Snew[d * 8 + 0], lf0[0], lf0[1], lf0[2], lf0[3]);  // edge p: s->d
    red_add_v4(&Snew[d * 8 + 4], lf0[4], lf0[5], lf0[6], lf0[7]);
    red_add_v4(&Snew[s * 8 + 0], lf1[0], lf1[1], lf1[2], lf1[3]);  // edge p+E2: d->s
    red_add_v4(&Snew[s * 8 + 4], lf1[4], lf1[5], lf1[6], lf1[7]);
}

// ---------------- BP init: f from m_0, lf_0, sum_in_0 -> buf[0] ----------------
__global__ __launch_bounds__(256) void bpA0_kernel(const int* __restrict__ ei)
{
    int p = blockIdx.x * 256 + threadIdx.x;
    if (p >= E2C) return;
    float m0[8], m1[8];
    {
        const float4* a = (const float4*)&g_m[(size_t)p * 8];
        float4 x0 = a[0], x1 = a[1];
        m0[0] = x0.x; m0[1] = x0.y; m0[2] = x0.z; m0[3] = x0.w;
        m0[4] = x1.x; m0[5] = x1.y; m0[6] = x1.z; m0[7] = x1.w;
        const float4* b = (const float4*)&g_m[(size_t)(E2C + p) * 8];
        float4 y0 = b[0], y1 = b[1];
        m1[0] = y0.x; m1[1] = y0.y; m1[2] = y0.z; m1[3] = y0.w;
        m1[4] = y1.x; m1[5] = y1.y; m1[6] = y1.z; m1[7] = y1.w;
    }
    float f0[8], f1[8];
    pair_factor(p, m0, m1, f0, f1);
    int s = ei[p], d = ei[EDIR + p];
    store_lf_red(p, s, d, g_norm[p], f0, f1, g_sumin2);
}

// ---------------- fused BP step: bpB(t) + bpA(t) ----------------
__device__ __forceinline__ void update_row(float* m, const float* lp, const float* S,
                                           const float* lf, float alpha)
{
    float lo[8], mx = -1e30f;
#pragma unroll
    for (int c = 0; c < 8; c++) {
        lo[c] = lp[c] + alpha * (S[c] - lf[c]);
        mx = fmaxf(mx, lo[c]);
    }
    float ex[8], sum = 0.f;
#pragma unroll
    for (int c = 0; c < 8; c++) { ex[c] = __expf(lo[c] - mx); sum += ex[c]; }
    float inv = __fdividef(1.f, sum);
    float s2 = 0.f;
#pragma unroll
    for (int c = 0; c < 8; c++) {
        m[c] = 0.8f * m[c] + 0.2f * ex[c] * inv;
        m[c] = fmaxf(m[c], 1e-12f);
        s2 += m[c];
    }
    float i2 = __fdividef(1.f, s2);
#pragma unroll
    for (int c = 0; c < 8; c++) m[c] *= i2;
}

__global__ __launch_bounds__(256) void bpF_kernel(const int* __restrict__ ei,
                                                  int rd, int wr)
{
    int p = blockIdx.x * 256 + threadIdx.x;
    if (p >= E2C) return;
    int s = ei[p], d = ei[EDIR + p];
    const float* Sold = g_sumin2 + (size_t)rd * (NN * CC);
    float*       Snew = g_sumin2 + (size_t)wr * (NN * CC);
    float alpha = g_alpha;

    float lf0[8], lf1[8];
    {
        const __half2* a = (const __half2*)&g_lfh[(size_t)p * 8];
        const __half2* b = (const __half2*)&g_lfh[(size_t)(E2C + p) * 8];
#pragma unroll
        for (int q = 0; q < 4; q++) {
            float2 u = __half22float2(a[q]);
            float2 v = __half22float2(b[q]);
            lf0[2 * q] = u.x; lf0[2 * q + 1] = u.y;
            lf1[2 * q] = v.x; lf1[2 * q + 1] = v.y;
        }
    }
    float Ss[8], Sd[8], lps[8], lpd[8];
    {
        const float4* c4 = (const float4*)&Sold[s * 8];
        float4 z0 = c4[0], z1 = c4[1];
        Ss[0] = z0.x; Ss[1] = z0.y; Ss[2] = z0.z; Ss[3] = z0.w;
        Ss[4] = z1.x; Ss[5] = z1.y; Ss[6] = z1.z; Ss[7] = z1.w;
        const float4* d4 = (const float4*)&Sold[d * 8];
        float4 w0 = d4[0], w1 = d4[1];
        Sd[0] = w0.x; Sd[1] = w0.y; Sd[2] = w0.z; Sd[3] = w0.w;
        Sd[4] = w1.x; Sd[5] = w1.y; Sd[6] = w1.z; Sd[7] = w1.w;
        const float4* e4 = (const float4*)&g_logphi[s * 8];
        float4 u0 = e4[0], u1 = e4[1];
        lps[0] = u0.x; lps[1] = u0.y; lps[2] = u0.z; lps[3] = u0.w;
        lps[4] = u1.x; lps[5] = u1.y; lps[6] = u1.z; lps[7] = u1.w;
        const float4* f4 = (const float4*)&g_logphi[d * 8];
        float4 v0 = f4[0], v1 = f4[1];
        lpd[0] = v0.x; lpd[1] = v0.y; lpd[2] = v0.z; lpd[3] = v0.w;
        lpd[4] = v1.x; lpd[5] = v1.y; lpd[6] = v1.z; lpd[7] = v1.w;
    }

    float m0[8], m1[8];
    {
        float4* a = (float4*)&g_m[(size_t)p * 8];
        float4 x0 = a[0], x1 = a[1];
        m0[0] = x0.x; m0[1] = x0.y; m0[2] = x0.z; m0[3] = x0.w;
        m0[4] = x1.x; m0[5] = x1.y; m0[6] = x1.z; m0[7] = x1.w;
        float4* b = (float4*)&g_m[(size_t)(E2C + p) * 8];
        float4 y0 = b[0], y1 = b[1];
        m1[0] = y0.x; m1[1] = y0.y; m1[2] = y0.z; m1[3] = y0.w;
        m1[4] = y1.x; m1[5] = y1.y; m1[6] = y1.z; m1[7] = y1.w;
    }
    update_row(m0, lps, Ss, lf1, alpha);   // edge p:    src=s, rev lf = lf1
    update_row(m1, lpd, Sd, lf0, alpha);   // edge p+E2: src=d, rev lf = lf0
    {
        float4* a = (float4*)&g_m[(size_t)p * 8];
        a[0] = make_float4(m0[0], m0[1], m0[2], m0[3]);
        a[1] = make_float4(m0[4], m0[5], m0[6], m0[7]);
        float4* b = (float4*)&g_m[(size_t)(E2C + p) * 8];
        b[0] = make_float4(m1[0], m1[1], m1[2], m1[3]);
        b[1] = make_float4(m1[4], m1[5], m1[6], m1[7]);
    }

    float f0[8], f1[8];
    pair_factor(p, m0, m1, f0, f1);
    store_lf_red(p, s, d, g_norm[p], f0, f1, Snew);
}

// ---------------- final beliefs (reads buf[0]) ----------------
__global__ void beliefs_kernel(float* __restrict__ out)
{
    int n = blockIdx.x * 256 + threadIdx.x;
    if (n >= NN) return;
    float alpha = g_alpha;
    const float* lp = &g_logphi[n * 8];
    const float* S  = &g_sumin2[n * 8];
    float l[8], mx = -1e30f;
#pragma unroll
    for (int c = 0; c < 8; c++) { l[c] = lp[c] + alpha * S[c]; mx = fmaxf(mx, l[c]); }
    float ex[8], sum = 0.f;
#pragma unroll
    for (int c = 0; c < 8; c++) { ex[c] = __expf(l[c] - mx); sum += ex[c]; }
    float inv = __fdividef(1.f, sum);
    float4* o = (float4*)&out[n * 8];
    o[0] = make_float4(ex[0] * inv, ex[1] * inv, ex[2] * inv, ex[3] * inv);
    o[1] = make_float4(ex[4] * inv, ex[5] * inv, ex[6] * inv, ex[7] * inv);
}

// ---------------- driver ----------------
extern "C" void kernel_launch(void* const* d_in, const int* in_sizes, int n_in,
                              void* d_out, int out_size)
{
    (void)in_sizes; (void)n_in; (void)out_size;
    const float* x       = (const float*)d_in[0];
    const int*   ei      = (const int*)d_in[1];
    // d_in[2] = rev: structurally known (i <-> i+E2), unused
    const float* enc_w1  = (const float*)d_in[3];
    const float* enc_b1  = (const float*)d_in[4];
    const float* enc_w2  = (const float*)d_in[5];
    const float* enc_b2  = (const float*)d_in[6];
    const float* edge_w1 = (const float*)d_in[7];
    const float* edge_b1 = (const float*)d_in[8];
    const float* edge_w2 = (const float*)d_in[9];
    const float* edge_b2 = (const float*)d_in[10];
    const float* R_raw   = (const float*)d_in[11];
    const float* rsl     = (const float*)d_in[12];
    const float* ml      = (const float*)d_in[13];
    float* out = (float*)d_out;

    const int PB = (E2C + 255) / 256;

    // resolve device-global addresses for memset nodes (host-side query; no alloc)
    void* deg_ptr = nullptr;
    void* sum_ptr = nullptr;
    cudaGetSymbolAddress(&deg_ptr, g_deg);
    cudaGetSymbolAddress(&sum_ptr, g_sumin2);
    float* sum0 = (float*)sum_ptr;
    float* sum1 = sum0 + (size_t)NN * CC;

    cudaMemsetAsync(deg_ptr, 0, (size_t)NN * sizeof(int));
    enc_gemm_kernel<<<(NN + 63) / 64, 256>>>(x, enc_w1, enc_b1);
    logphi_kernel<<<(NN + 7) / 8, 256>>>(enc_w2, enc_b2);
    degcount_kernel<<<EDIR / 256, 256>>>(ei);
    degpost_kernel<<<(NN + 255) / 256, 256>>>();
    prepR_kernel<<<1, 64>>>(R_raw, rsl, ml);
    edgemlp_kernel<<<(E2C + 255) / 256, 256>>>(ei, edge_w1, edge_b1, edge_w2, edge_b2);
    edgeprep_kernel<<<PB, 256>>>(ei);

    // t = 0: factors + sum_in from initial messages -> buf 0
    cudaMemsetAsync(sum0, 0, (size_t)NN * CC * sizeof(float));
    bpA0_kernel<<<PB, 256>>>(ei);

    // t = 1..10: fused update + re-factor, ping-ponging sum_in buffers.
    // After t = 10 the freshest sum_in (from m_10) is in buf 0.
    for (int t = 1; t <= TT; t++) {
        int rd = (t - 1) & 1, wr = t & 1;
        cudaMemsetAsync(wr ? sum1 : sum0, 0, (size_t)NN * CC * sizeof(float));
        bpF_kernel<<<PB, 256>>>(ei, rd, wr);
    }
    beliefs_kernel<<<(NN + 255) / 256, 256>>>(out);
}